// round 2
// baseline (speedup 1.0000x reference)
#include <cuda_runtime.h>
#include <math.h>

#define HH   112
#define WW   512
#define CI   64
#define CLm  32
#define NPIX (HH*WW)      // 57344
#define M1   (HH*16)      // 1792
#define KD   (HH*CLm)     // 3584

// ---------------- scratch (static device globals; no allocation) ----------------
__device__ float  g_hf[KD*WW];        // [3584,512]  stage-1 output (hf)
__device__ float  g_x1[M1*WW];        // [1792,512]  d3 output
__device__ float  g_xt[NPIX*CI];      // [pix,64]    transposed input
__device__ int    g_inds1[NPIX];
__device__ int    g_inds12[NPIX];     // UNCLIPPED inds12
__device__ double g_acc[16];          // [0]=ce1 nll, [1..6]=branch nll, [8..13]=branch mask

// ---------------- helpers ----------------
__device__ __forceinline__ float leakyf(float v){ return v > 0.f ? v : 0.01f*v; }

// one-warp expert MLP: 64->32 (leaky) ->32 (leaky) ->32 ; returns this lane's logit
__device__ __forceinline__ float expert_fwd(
    const float* __restrict__ xt,
    const float* __restrict__ w1, const float* __restrict__ b1,
    const float* __restrict__ w2, const float* __restrict__ b2,
    const float* __restrict__ w3, const float* __restrict__ b3,
    int lane)
{
    const unsigned FULL = 0xffffffffu;
    float xa = xt[lane];
    float xb = xt[32 + lane];
    float y1 = b1[lane];
#pragma unroll
    for (int i = 0; i < 32; i++)
        y1 = fmaf(__shfl_sync(FULL, xa, i), w1[i*32 + lane], y1);
#pragma unroll
    for (int i = 0; i < 32; i++)
        y1 = fmaf(__shfl_sync(FULL, xb, i), w1[(i+32)*32 + lane], y1);
    y1 = leakyf(y1);
    float y2 = b2[lane];
#pragma unroll
    for (int i = 0; i < 32; i++)
        y2 = fmaf(__shfl_sync(FULL, y1, i), w2[i*32 + lane], y2);
    y2 = leakyf(y2);
    float y3 = b3[lane];
#pragma unroll
    for (int i = 0; i < 32; i++)
        y3 = fmaf(__shfl_sync(FULL, y2, i), w3[i*32 + lane], y3);
    return y3;
}

// ---------------- K0: zero accumulators ----------------
__global__ void k_zero()
{
    if (threadIdx.x < 16) g_acc[threadIdx.x] = 0.0;
}

// ---------------- K1: transpose x_in [ci,H,W] -> g_xt [pix,ci] ----------------
__global__ void k_transpose(const float* __restrict__ x_in)
{
    __shared__ float tile[32][33];
    int p0 = blockIdx.x * 32;
    int i0 = blockIdx.y * 32;
    int tx = threadIdx.x, ty = threadIdx.y;
#pragma unroll
    for (int r = ty; r < 32; r += 8)
        tile[r][tx] = x_in[(size_t)(i0 + r) * NPIX + p0 + tx];
    __syncthreads();
#pragma unroll
    for (int r = ty; r < 32; r += 8)
        g_xt[(size_t)(p0 + r) * CI + i0 + tx] = tile[tx][r];
}

// ---------------- K2: stage-1 grouped convs -> g_hf ----------------
__global__ void k_stage1(const float* __restrict__ x_in,
                         const float* __restrict__ g1w, const float* __restrict__ g1b,
                         const float* __restrict__ g2w, const float* __restrict__ g2b)
{
    __shared__ float w1T[CI*CLm];   // [i][o]
    __shared__ float w2T[CLm*CLm];  // [i][o]
    __shared__ float b1s[CLm], b2s[CLm];
    int h = blockIdx.x, tid = threadIdx.x;
    for (int idx = tid; idx < CI*CLm; idx += 128) {
        int o = idx >> 6, i = idx & 63;
        w1T[i*CLm + o] = g1w[(size_t)h*CI*CLm + idx];
    }
    for (int idx = tid; idx < CLm*CLm; idx += 128) {
        int o = idx >> 5, i = idx & 31;
        w2T[i*CLm + o] = g2w[(size_t)h*CLm*CLm + idx];
    }
    if (tid < CLm) { b1s[tid] = g1b[h*CLm + tid]; b2s[tid] = g2b[h*CLm + tid]; }
    __syncthreads();

    for (int w = tid; w < WW; w += 128) {
        float h1[CLm];
#pragma unroll
        for (int o = 0; o < CLm; o++) h1[o] = b1s[o];
#pragma unroll 4
        for (int i = 0; i < CI; i++) {
            float xi = x_in[(size_t)i*NPIX + h*WW + w];
#pragma unroll
            for (int o = 0; o < CLm; o++) h1[o] = fmaf(xi, w1T[i*CLm + o], h1[o]);
        }
#pragma unroll
        for (int o = 0; o < CLm; o++) h1[o] = leakyf(h1[o]);
        float h2[CLm];
#pragma unroll
        for (int o = 0; o < CLm; o++) h2[o] = b2s[o];
#pragma unroll 4
        for (int i = 0; i < CLm; i++) {
            float v = h1[i];
#pragma unroll
            for (int o = 0; o < CLm; o++) h2[o] = fmaf(v, w2T[i*CLm + o], h2[o]);
        }
#pragma unroll
        for (int o = 0; o < CLm; o++)
            g_hf[(size_t)(h*CLm + o)*WW + w] = leakyf(h2[o]);
    }
}

// ---------------- K3: d3 dense GEMM  g_x1 = d3_w @ g_hf + d3_b ----------------
// A = d3_w [1792 x 3584] row-major, B = g_hf [3584 x 512], C = g_x1 [1792 x 512]
// BM=32 BN=64 BK=16, 128 threads, TM=4 TN=4; grid (56, 8)
__global__ void k_gemm(const float* __restrict__ A, const float* __restrict__ bias)
{
    __shared__ float As[16][32];
    __shared__ float Bs[16][64];
    int tid = threadIdx.x;
    int tx = tid & 15, ty = tid >> 4;              // tx 0..15, ty 0..7
    int bm = blockIdx.x * 32, bn = blockIdx.y * 64;
    float acc[4][4] = {};
    const float* Ap = A + (size_t)bm * KD;
    int arow = tid >> 2, acol = (tid & 3) * 4;

    for (int k0 = 0; k0 < KD; k0 += 16) {
        float4 a4 = *(const float4*)(Ap + (size_t)arow*KD + k0 + acol);
        As[acol + 0][arow] = a4.x;
        As[acol + 1][arow] = a4.y;
        As[acol + 2][arow] = a4.z;
        As[acol + 3][arow] = a4.w;
#pragma unroll
        for (int r = 0; r < 2; r++) {
            int idx = r*512 + tid*4;
            int kk = idx >> 6, nn = idx & 63;
            *(float4*)&Bs[kk][nn] =
                *(const float4*)(g_hf + (size_t)(k0 + kk)*WW + bn + nn);
        }
        __syncthreads();
#pragma unroll
        for (int k = 0; k < 16; k++) {
            float4 ra = *(const float4*)&As[k][ty*4];
            float4 rb = *(const float4*)&Bs[k][tx*4];
            float av[4] = {ra.x, ra.y, ra.z, ra.w};
            float bv[4] = {rb.x, rb.y, rb.z, rb.w};
#pragma unroll
            for (int i = 0; i < 4; i++)
#pragma unroll
                for (int j = 0; j < 4; j++)
                    acc[i][j] = fmaf(av[i], bv[j], acc[i][j]);
        }
        __syncthreads();
    }
#pragma unroll
    for (int i = 0; i < 4; i++) {
        int row = bm + ty*4 + i;
        float bsv = bias[row];
        float4 v = make_float4(acc[i][0]+bsv, acc[i][1]+bsv, acc[i][2]+bsv, acc[i][3]+bsv);
        *(float4*)(g_x1 + (size_t)row*WW + bn + tx*4) = v;
    }
}

// ---------------- K4: stage-1 argmax + CE loss (loss[0]) ----------------
__global__ void k_s1head(const int* __restrict__ inds_gt)
{
    int pix = blockIdx.x * 256 + threadIdx.x;
    int h = pix >> 9, w = pix & 511;
    float v[16];
    float mx = -1e30f; int mi = 0;
#pragma unroll
    for (int c = 0; c < 16; c++) {
        v[c] = g_x1[(size_t)(h*16 + c)*WW + w];
        if (v[c] > mx) { mx = v[c]; mi = c; }
    }
    g_inds1[pix] = mi;
    int g = min(max(inds_gt[pix], 0), 4095);
    int t = g >> 8;                      // inds_gt // 256
    float s = 0.f;
#pragma unroll
    for (int c = 0; c < 16; c++) s += expf(v[c] - mx);
    float nll = mx + logf(s) - v[t];

    __shared__ float red[256];
    red[threadIdx.x] = nll;
    __syncthreads();
    for (int o = 128; o; o >>= 1) {
        if (threadIdx.x < o) red[threadIdx.x] += red[threadIdx.x + o];
        __syncthreads();
    }
    if (threadIdx.x == 0) atomicAdd(&g_acc[0], (double)red[0]);
}

// ---------------- K5: stage-2 forward -> inds12 ----------------
__global__ void k_stage2(const float* __restrict__ w1, const float* __restrict__ b1,
                         const float* __restrict__ w2, const float* __restrict__ b2,
                         const float* __restrict__ w3, const float* __restrict__ b3)
{
    int pix  = (blockIdx.x * blockDim.x + threadIdx.x) >> 5;
    int lane = threadIdx.x & 31;
    int h = pix >> 9;
    int i1 = g_inds1[pix];
    size_t e = (size_t)(i1 + 16*h);
    float y = expert_fwd(g_xt + (size_t)pix*CI,
                         w1 + e*2048, b1 + e*32, w2 + e*1024, b2 + e*32,
                         w3 + e*1024, b3 + e*32, lane);
    float bvv = y; int bi = lane;
#pragma unroll
    for (int off = 16; off; off >>= 1) {
        float ov = __shfl_xor_sync(0xffffffffu, bvv, off);
        int   oi = __shfl_xor_sync(0xffffffffu, bi, off);
        if (ov > bvv || (ov == bvv && oi < bi)) { bvv = ov; bi = oi; }
    }
    if (lane == 0) g_inds12[pix] = i1*16 + bi - 8;   // unclipped
}

// ---------------- K6: stage-3 forward -> output indices ----------------
__global__ void k_stage3(const float* __restrict__ w1, const float* __restrict__ b1,
                         const float* __restrict__ w2, const float* __restrict__ b2,
                         const float* __restrict__ w3, const float* __restrict__ b3,
                         float* __restrict__ outF)
{
    int pix  = (blockIdx.x * blockDim.x + threadIdx.x) >> 5;
    int lane = threadIdx.x & 31;
    int h = pix >> 9;
    int i12 = g_inds12[pix];
    size_t e = (size_t)(min(max(i12, 0), 255) + 256*h);
    float y = expert_fwd(g_xt + (size_t)pix*CI,
                         w1 + e*2048, b1 + e*32, w2 + e*1024, b2 + e*32,
                         w3 + e*1024, b3 + e*32, lane);
    float bvv = y; int bi = lane;
#pragma unroll
    for (int off = 16; off; off >>= 1) {
        float ov = __shfl_xor_sync(0xffffffffu, bvv, off);
        int   oi = __shfl_xor_sync(0xffffffffu, bi, off);
        if (ov > bvv || (ov == bvv && oi < bi)) { bvv = ov; bi = oi; }
    }
    if (lane == 0) {
        int v = min(max(i12*16 + bi - 8, 0), 4095);
        outF[pix] = (float)v;
    }
}

// ---------------- K7: 6 loss branches (gridDim.y = branch) ----------------
__global__ void k_loss(const int* __restrict__ inds_gt,
                       const float* __restrict__ s2w1, const float* __restrict__ s2b1,
                       const float* __restrict__ s2w2, const float* __restrict__ s2b2,
                       const float* __restrict__ s2w3, const float* __restrict__ s2b3,
                       const float* __restrict__ s3w1, const float* __restrict__ s3b1,
                       const float* __restrict__ s3w2, const float* __restrict__ s3b2,
                       const float* __restrict__ s3w3, const float* __restrict__ s3b3)
{
    int b    = blockIdx.y;                          // 0..5
    int pix  = (blockIdx.x * blockDim.x + threadIdx.x) >> 5;
    int lane = threadIdx.x & 31;
    int h = pix >> 9;
    int g = min(max(inds_gt[pix], 0), 4095);

    const float *w1, *bb1, *w2, *bb2, *w3, *bb3;
    int t, mask;
    if (b < 3) {
        int i  = b - 1;
        int i1 = min(max((g >> 8) + i, 0), 15);
        int tr = (g >> 4) - i1*16 + 8;
        mask = (tr >= 0 && tr < 32) ? 1 : 0;
        t = min(max(tr, 0), 31);
        size_t e = (size_t)(i1 + 16*h);
        w1 = s2w1 + e*2048; bb1 = s2b1 + e*32;
        w2 = s2w2 + e*1024; bb2 = s2b2 + e*32;
        w3 = s2w3 + e*1024; bb3 = s2b3 + e*32;
    } else {
        int i   = b - 4;
        int i12 = min(max((g >> 4) + i, 0), 255);
        int tr  = g - i12*16 + 8;
        mask = (tr >= 0 && tr < 32) ? 1 : 0;
        t = min(max(tr, 0), 31);
        size_t e = (size_t)(i12 + 256*h);
        w1 = s3w1 + e*2048; bb1 = s3b1 + e*32;
        w2 = s3w2 + e*1024; bb2 = s3b2 + e*32;
        w3 = s3w3 + e*1024; bb3 = s3b3 + e*32;
    }
    float y = expert_fwd(g_xt + (size_t)pix*CI, w1, bb1, w2, bb2, w3, bb3, lane);

    float m = y;
#pragma unroll
    for (int off = 16; off; off >>= 1) m = fmaxf(m, __shfl_xor_sync(0xffffffffu, m, off));
    float s = expf(y - m);
#pragma unroll
    for (int off = 16; off; off >>= 1) s += __shfl_xor_sync(0xffffffffu, s, off);
    float vt = __shfl_sync(0xffffffffu, y, t);
    float nll = m + logf(s) - vt;

    __shared__ float s_n[8];
    __shared__ int   s_m[8];
    if (lane == 0) { s_n[threadIdx.x >> 5] = nll; s_m[threadIdx.x >> 5] = mask; }
    __syncthreads();
    if (threadIdx.x == 0) {
        float sn = 0.f; int sm = 0;
#pragma unroll
        for (int k = 0; k < 8; k++) { sn += s_n[k]; sm += s_m[k]; }
        atomicAdd(&g_acc[1 + b], (double)sn);
        atomicAdd(&g_acc[8 + b], (double)sm);
    }
}

// ---------------- K8: finalize losses ----------------
__global__ void k_final(float* __restrict__ outF, int base)
{
    if (threadIdx.x == 0) {
        double N = (double)NPIX;
        outF[base] = (float)(g_acc[0] / N);
#pragma unroll
        for (int b = 0; b < 6; b++)
            outF[base + 1 + b] = (float)((g_acc[1 + b] / N) * (g_acc[8 + b] / N));
    }
}

// ---------------- launcher ----------------
extern "C" void kernel_launch(void* const* d_in, const int* in_sizes, int n_in,
                              void* d_out, int out_size)
{
    const float* x_in  = (const float*)d_in[0];
    const float* g1_w  = (const float*)d_in[1];
    const float* g1_b  = (const float*)d_in[2];
    const float* g2_w  = (const float*)d_in[3];
    const float* g2_b  = (const float*)d_in[4];
    const float* d3_w  = (const float*)d_in[5];
    const float* d3_b  = (const float*)d_in[6];
    const float* s2_w1 = (const float*)d_in[7];
    const float* s2_b1 = (const float*)d_in[8];
    const float* s2_w2 = (const float*)d_in[9];
    const float* s2_b2 = (const float*)d_in[10];
    const float* s2_w3 = (const float*)d_in[11];
    const float* s2_b3 = (const float*)d_in[12];
    const float* s3_w1 = (const float*)d_in[13];
    const float* s3_b1 = (const float*)d_in[14];
    const float* s3_w2 = (const float*)d_in[15];
    const float* s3_b2 = (const float*)d_in[16];
    const float* s3_w3 = (const float*)d_in[17];
    const float* s3_b3 = (const float*)d_in[18];
    const int*   igt   = (const int*)d_in[19];
    float* outF = (float*)d_out;

    k_zero<<<1, 32>>>();
    k_transpose<<<dim3(NPIX/32, CI/32), dim3(32, 8)>>>(x_in);
    k_stage1<<<HH, 128>>>(x_in, g1_w, g1_b, g2_w, g2_b);
    k_gemm<<<dim3(M1/32, WW/64), 128>>>(d3_w, d3_b);
    k_s1head<<<NPIX/256, 256>>>(igt);
    k_stage2<<<NPIX/8, 256>>>(s2_w1, s2_b1, s2_w2, s2_b2, s2_w3, s2_b3);
    k_stage3<<<NPIX/8, 256>>>(s3_w1, s3_b1, s3_w2, s3_b2, s3_w3, s3_b3, outF);
    k_loss<<<dim3(NPIX/8, 6), 256>>>(igt,
        s2_w1, s2_b1, s2_w2, s2_b2, s2_w3, s2_b3,
        s3_w1, s3_b1, s3_w2, s3_b2, s3_w3, s3_b3);
    k_final<<<1, 32>>>(outF, out_size - 7);
}